// round 1
// baseline (speedup 1.0000x reference)
#include <cuda_runtime.h>
#include <cstdint>

// Problem constants
#define BB 16
#define CC 8
#define TT 4096
#define KK 64
#define LL 128
#define TP (TT - LL + 1)      // 3969 valid sliding positions
#define TCHUNK 256            // t' positions per CTA
#define NCHUNK ((TP + TCHUNK - 1) / TCHUNK)   // 16

__global__ void init_out_kernel(int* out) {
    int i = blockIdx.x * 256 + threadIdx.x;
    if (i < BB * KK) out[i] = 0x7F800000;  // +inf bits
}

__global__ __launch_bounds__(256, 2)
void shapelet_min_kernel(const float* __restrict__ X,
                         const float* __restrict__ S,
                         float* __restrict__ out) {
    __shared__ float sT[LL][KK];          // shapelets transposed: [l][k]
    __shared__ float xs[TCHUNK + LL];     // channel-sum of x for this chunk (384)
    __shared__ float xq[TCHUNK + LL];     // channel-sum of x^2
    __shared__ float ws[TCHUNK];          // sliding window sum of xq (length L)
    __shared__ float offs[KK];            // C * sum_l s[k,l]^2

    const int tid   = threadIdx.x;
    const int b     = blockIdx.y;
    const int chunk = blockIdx.x;
    const int tbase = chunk * TCHUNK;

    // ---- Prologue 1: shapelets -> smem transposed ----
    {
        int k  = tid & 63;
        int lg = tid >> 6;                         // 0..3
        const float4* S4 = (const float4*)(S + k * LL);
        #pragma unroll
        for (int j = 0; j < 8; j++) {
            int l4 = lg + j * 4;                   // 0..31
            float4 v = S4[l4];
            int l = l4 * 4;
            sT[l + 0][k] = v.x;
            sT[l + 1][k] = v.y;
            sT[l + 2][k] = v.z;
            sT[l + 3][k] = v.w;
        }
    }

    // ---- Prologue 2: channel sums of x and x^2 for [tbase, tbase+384) ----
    for (int t = tid; t < TCHUNK + LL; t += 256) {
        int tg = tbase + t;
        float sm = 0.f, sq = 0.f;
        if (tg < TT) {
            #pragma unroll
            for (int c = 0; c < CC; c++) {
                float v = X[((b * CC + c) << 12) + tg];
                sm += v;
                sq += v * v;
            }
        }
        xs[t] = sm;
        xq[t] = sq;
    }
    __syncthreads();

    // ---- Prologue 3: sliding window sums + shapelet norms ----
    if (tid < 64) {
        int st = tid * 4;
        float a = 0.f;
        #pragma unroll
        for (int i = 0; i < LL; i++) a += xq[st + i];
        ws[st] = a;
        #pragma unroll
        for (int j = 1; j < 4; j++) {
            a += xq[st + LL + j - 1] - xq[st + j - 1];
            ws[st + j] = a;
        }
    } else if (tid < 128) {
        int k = tid - 64;
        float a = 0.f;
        #pragma unroll
        for (int l = 0; l < LL; l++) {
            float v = sT[l][k];
            a += v * v;
        }
        offs[k] = (float)CC * a;
    }
    __syncthreads();

    // ---- Main loop: corr[t_local, k] = sum_l xs[t_local + l] * sT[l][k] ----
    const int tg = tid & 31;      // lane: t-group, covers t_local = tg*8 + 0..7
    const int kg = tid >> 5;      // warp id: k-group, k = kg*8 + 0..7
    const int kb = kg * 8;
    const float* xp = xs + tg * 8;   // 32B aligned

    float acc[8][8];
    #pragma unroll
    for (int i = 0; i < 8; i++)
        #pragma unroll
        for (int j = 0; j < 8; j++)
            acc[i][j] = 0.f;

    #pragma unroll 2
    for (int l = 0; l < LL; l += 4) {
        float4 xa = *(const float4*)(xp + l);
        float4 xb = *(const float4*)(xp + l + 4);
        float4 xc = *(const float4*)(xp + l + 8);
        float xr[12] = {xa.x, xa.y, xa.z, xa.w,
                        xb.x, xb.y, xb.z, xb.w,
                        xc.x, xc.y, xc.z, xc.w};
        #pragma unroll
        for (int j = 0; j < 4; j++) {
            float4 s0 = *(const float4*)&sT[l + j][kb];
            float4 s1 = *(const float4*)&sT[l + j][kb + 4];
            float sv[8] = {s0.x, s0.y, s0.z, s0.w, s1.x, s1.y, s1.z, s1.w};
            #pragma unroll
            for (int t8 = 0; t8 < 8; t8++) {
                float xv = xr[j + t8];
                #pragma unroll
                for (int k8 = 0; k8 < 8; k8++)
                    acc[t8][k8] = fmaf(xv, sv[k8], acc[t8][k8]);
            }
        }
    }

    // ---- Epilogue: agg = ws - 2*corr, min over t', warp-reduce, atomicMin ----
    float m[8];
    #pragma unroll
    for (int k8 = 0; k8 < 8; k8++) m[k8] = __int_as_float(0x7F800000);

    #pragma unroll
    for (int t8 = 0; t8 < 8; t8++) {
        int tl = tg * 8 + t8;
        if (tbase + tl < TP) {
            float w = ws[tl];
            #pragma unroll
            for (int k8 = 0; k8 < 8; k8++)
                m[k8] = fminf(m[k8], fmaf(-2.f, acc[t8][k8], w));
        }
    }

    #pragma unroll
    for (int k8 = 0; k8 < 8; k8++) {
        #pragma unroll
        for (int o = 16; o > 0; o >>= 1)
            m[k8] = fminf(m[k8], __shfl_xor_sync(0xffffffffu, m[k8], o));
    }

    if (tg == 0) {
        #pragma unroll
        for (int k8 = 0; k8 < 8; k8++) {
            float v = m[k8] + offs[kb + k8];
            atomicMin((int*)&out[b * KK + kb + k8], __float_as_int(v));
        }
    }
}

extern "C" void kernel_launch(void* const* d_in, const int* in_sizes, int n_in,
                              void* d_out, int out_size) {
    const float* X = (const float*)d_in[0];   // (16, 8, 4096) f32
    const float* S = (const float*)d_in[1];   // (64, 128) f32
    float* out = (float*)d_out;               // (16, 64) f32

    init_out_kernel<<<(BB * KK + 255) / 256, 256>>>((int*)out);
    dim3 grid(NCHUNK, BB);
    shapelet_min_kernel<<<grid, 256>>>(X, S, out);
}

// round 2
// speedup vs baseline: 1.1330x; 1.1330x over previous
#include <cuda_runtime.h>
#include <cstdint>

// Problem constants
#define BB 16
#define CC 8
#define TT 4096
#define KK 64
#define LL 128
#define TP (TT - LL + 1)      // 3969 valid sliding positions
#define TCHUNK 256            // t' positions per CTA
#define NCHUNK ((TP + TCHUNK - 1) / TCHUNK)   // 16

typedef unsigned long long u64;

__device__ __forceinline__ u64 pack2(float v) {
    u64 r;
    asm("mov.b64 %0, {%1, %1};" : "=l"(r) : "f"(v));
    return r;
}

__device__ __forceinline__ void fma2(u64 &d, u64 a, u64 b) {
    asm("fma.rn.f32x2 %0, %1, %2, %0;" : "+l"(d) : "l"(a), "l"(b));
}

__device__ __forceinline__ float2 unpack2(u64 v) {
    float2 r;
    asm("mov.b64 {%0, %1}, %2;" : "=f"(r.x), "=f"(r.y) : "l"(v));
    return r;
}

__global__ void init_out_kernel(int* out) {
    int i = blockIdx.x * 256 + threadIdx.x;
    if (i < BB * KK) out[i] = 0x7F800000;  // +inf bits
}

__global__ __launch_bounds__(256, 2)
void shapelet_min_kernel(const float* __restrict__ X,
                         const float* __restrict__ S,
                         float* __restrict__ out) {
    __shared__ float sT[LL][KK];          // shapelets transposed: [l][k]
    __shared__ float xs[TCHUNK + LL];     // channel-sum of x for this chunk (384)
    __shared__ float xq[TCHUNK + LL];     // channel-sum of x^2
    __shared__ float ws[TCHUNK];          // sliding window sum of xq (length L)
    __shared__ float offs[KK];            // C * sum_l s[k,l]^2

    const int tid   = threadIdx.x;
    const int b     = blockIdx.y;
    const int chunk = blockIdx.x;
    const int tbase = chunk * TCHUNK;

    // ---- Prologue 1: shapelets -> smem transposed ----
    {
        int k  = tid & 63;
        int lg = tid >> 6;                         // 0..3
        const float4* S4 = (const float4*)(S + k * LL);
        #pragma unroll
        for (int j = 0; j < 8; j++) {
            int l4 = lg + j * 4;                   // 0..31
            float4 v = S4[l4];
            int l = l4 * 4;
            sT[l + 0][k] = v.x;
            sT[l + 1][k] = v.y;
            sT[l + 2][k] = v.z;
            sT[l + 3][k] = v.w;
        }
    }

    // ---- Prologue 2: channel sums of x and x^2 for [tbase, tbase+384) ----
    for (int t = tid; t < TCHUNK + LL; t += 256) {
        int tg = tbase + t;
        float sm = 0.f, sq = 0.f;
        if (tg < TT) {
            #pragma unroll
            for (int c = 0; c < CC; c++) {
                float v = X[((b * CC + c) << 12) + tg];
                sm += v;
                sq += v * v;
            }
        }
        xs[t] = sm;
        xq[t] = sq;
    }
    __syncthreads();

    // ---- Prologue 3: sliding window sums + shapelet norms ----
    if (tid < 64) {
        int st = tid * 4;
        float a = 0.f;
        #pragma unroll
        for (int i = 0; i < LL; i++) a += xq[st + i];
        ws[st] = a;
        #pragma unroll
        for (int j = 1; j < 4; j++) {
            a += xq[st + LL + j - 1] - xq[st + j - 1];
            ws[st + j] = a;
        }
    } else if (tid < 128) {
        int k = tid - 64;
        float a = 0.f;
        #pragma unroll
        for (int l = 0; l < LL; l++) {
            float v = sT[l][k];
            a += v * v;
        }
        offs[k] = (float)CC * a;
    }
    __syncthreads();

    // ---- Main loop: corr[t_local, k] = sum_l xs[t_local + l] * sT[l][k] ----
    // Packed f32x2 over k: each thread owns 8 t' x 4 k-pairs (= 8 k).
    const int tg = tid & 31;      // lane: t-group, covers t_local = tg*8 + 0..7
    const int kg = tid >> 5;      // warp id: k-group, k = kg*8 + 0..7
    const int kb = kg * 8;
    const float* xp = xs + tg * 8;   // 32B aligned

    u64 acc[8][4];
    #pragma unroll
    for (int i = 0; i < 8; i++)
        #pragma unroll
        for (int p = 0; p < 4; p++)
            acc[i][p] = 0ull;

    #pragma unroll 2
    for (int l = 0; l < LL; l += 4) {
        float4 xa = *(const float4*)(xp + l);
        float4 xb = *(const float4*)(xp + l + 4);
        float4 xc = *(const float4*)(xp + l + 8);
        u64 xr2[12];
        xr2[0]  = pack2(xa.x); xr2[1]  = pack2(xa.y); xr2[2]  = pack2(xa.z); xr2[3]  = pack2(xa.w);
        xr2[4]  = pack2(xb.x); xr2[5]  = pack2(xb.y); xr2[6]  = pack2(xb.z); xr2[7]  = pack2(xb.w);
        xr2[8]  = pack2(xc.x); xr2[9]  = pack2(xc.y); xr2[10] = pack2(xc.z); xr2[11] = pack2(xc.w);
        #pragma unroll
        for (int j = 0; j < 4; j++) {
            // 8 consecutive shapelet values for this l as 4 packed pairs (warp-broadcast LDS)
            ulonglong2 u0 = *(const ulonglong2*)&sT[l + j][kb];
            ulonglong2 u1 = *(const ulonglong2*)&sT[l + j][kb + 4];
            u64 sv2[4] = {u0.x, u0.y, u1.x, u1.y};
            #pragma unroll
            for (int t8 = 0; t8 < 8; t8++) {
                u64 xv2 = xr2[j + t8];
                #pragma unroll
                for (int p = 0; p < 4; p++)
                    fma2(acc[t8][p], xv2, sv2[p]);
            }
        }
    }

    // ---- Epilogue: agg = ws - 2*corr, min over t', warp-reduce, atomicMin ----
    float m[8];
    #pragma unroll
    for (int k8 = 0; k8 < 8; k8++) m[k8] = __int_as_float(0x7F800000);

    #pragma unroll
    for (int t8 = 0; t8 < 8; t8++) {
        int tl = tg * 8 + t8;
        if (tbase + tl < TP) {
            float w = ws[tl];
            #pragma unroll
            for (int p = 0; p < 4; p++) {
                float2 c = unpack2(acc[t8][p]);
                m[2 * p + 0] = fminf(m[2 * p + 0], fmaf(-2.f, c.x, w));
                m[2 * p + 1] = fminf(m[2 * p + 1], fmaf(-2.f, c.y, w));
            }
        }
    }

    #pragma unroll
    for (int k8 = 0; k8 < 8; k8++) {
        #pragma unroll
        for (int o = 16; o > 0; o >>= 1)
            m[k8] = fminf(m[k8], __shfl_xor_sync(0xffffffffu, m[k8], o));
    }

    if (tg == 0) {
        #pragma unroll
        for (int k8 = 0; k8 < 8; k8++) {
            float v = m[k8] + offs[kb + k8];
            atomicMin((int*)&out[b * KK + kb + k8], __float_as_int(v));
        }
    }
}

extern "C" void kernel_launch(void* const* d_in, const int* in_sizes, int n_in,
                              void* d_out, int out_size) {
    const float* X = (const float*)d_in[0];   // (16, 8, 4096) f32
    const float* S = (const float*)d_in[1];   // (64, 128) f32
    float* out = (float*)d_out;               // (16, 64) f32

    init_out_kernel<<<(BB * KK + 255) / 256, 256>>>((int*)out);
    dim3 grid(NCHUNK, BB);
    shapelet_min_kernel<<<grid, 256>>>(X, S, out);
}

// round 4
// speedup vs baseline: 2.1465x; 1.8945x over previous
#include <cuda_runtime.h>
#include <cstdint>
#include <math_constants.h>

// Problem constants
#define BB 16
#define CC 8
#define TT 4096
#define KK 64
#define LL 128
#define TP (TT - LL + 1)        // 3969 valid sliding positions
#define TCHUNK 256              // t' per CTA
#define NCHUNK 16               // ceil(3969/256)
#define SSTR 132                // padded shapelet row stride (floats) -> conflict-free B loads

typedef unsigned int u32;

__device__ __forceinline__ u32 f2tf32(float v) {
    u32 r;
    asm("cvt.rna.tf32.f32 %0, %1;" : "=r"(r) : "f"(v));
    return r;
}

__device__ __forceinline__ void mma_tf32(float* c, u32 a0, u32 a1, u32 a2, u32 a3,
                                         u32 b0, u32 b1) {
    asm volatile(
        "mma.sync.aligned.m16n8k8.row.col.f32.tf32.tf32.f32 "
        "{%0,%1,%2,%3}, {%4,%5,%6,%7}, {%8,%9}, {%0,%1,%2,%3};"
        : "+f"(c[0]), "+f"(c[1]), "+f"(c[2]), "+f"(c[3])
        : "r"(a0), "r"(a1), "r"(a2), "r"(a3), "r"(b0), "r"(b1));
}

__global__ void init_out_kernel(int* out) {
    int i = blockIdx.x * 256 + threadIdx.x;
    if (i < BB * KK) out[i] = 0x7F800000;  // +inf bits
}

__global__ __launch_bounds__(256, 2)
void shapelet_hmma_kernel(const float* __restrict__ X,
                          const float* __restrict__ S,
                          float* __restrict__ out) {
    __shared__ float sS[KK * SSTR];      // shapelets, tf32-rounded, padded stride
    __shared__ float xs[TCHUNK + LL];    // channel-sum of x (tf32-rounded)
    __shared__ float xq[TCHUNK + LL];    // channel-sum of x^2 (full f32)
    __shared__ float ws[TCHUNK];         // window sums (+inf past TP)
    __shared__ float offs[KK];           // C * sum_l s^2 (full f32)
    __shared__ float red[8 * KK];        // per-warp partial mins

    const int tid  = threadIdx.x;
    const int wid  = tid >> 5;
    const int lane = tid & 31;
    const int g    = lane >> 2;          // groupID 0..7
    const int t    = lane & 3;           // threadID_in_group 0..3
    const int b    = blockIdx.y;
    const int tbase = blockIdx.x * TCHUNK;

    // ---- Prologue 1: shapelets -> smem (tf32-rounded), shapelet norms ----
    {
        int k = tid >> 2;                // 0..63
        int q = tid & 3;                 // quarter of the 128-long row
        const float4* Sr = (const float4*)(S + k * LL + q * 32);
        float* dst = sS + k * SSTR + q * 32;
        float sq = 0.f;
        #pragma unroll
        for (int i = 0; i < 8; i++) {
            float4 v = Sr[i];
            sq += v.x * v.x + v.y * v.y + v.z * v.z + v.w * v.w;
            float4 w;
            w.x = __uint_as_float(f2tf32(v.x));
            w.y = __uint_as_float(f2tf32(v.y));
            w.z = __uint_as_float(f2tf32(v.z));
            w.w = __uint_as_float(f2tf32(v.w));
            *(float4*)(dst + i * 4) = w;
        }
        sq += __shfl_xor_sync(0xffffffffu, sq, 1);
        sq += __shfl_xor_sync(0xffffffffu, sq, 2);
        if (q == 0) offs[k] = (float)CC * sq;
    }

    // ---- Prologue 2: channel sums for t in [tbase, tbase+384) ----
    for (int j = tid; j < TCHUNK + LL; j += 256) {
        int tg = tbase + j;
        float sm = 0.f, sq = 0.f;
        if (tg < TT) {
            #pragma unroll
            for (int c = 0; c < CC; c++) {
                float v = X[((b * CC + c) << 12) + tg];
                sm += v; sq += v * v;
            }
        }
        xs[j] = __uint_as_float(f2tf32(sm));
        xq[j] = sq;
    }
    __syncthreads();

    // ---- Prologue 3: sliding window sums (with +inf mask past TP) ----
    if (tid < 64) {
        int j0 = tid * 4;
        float a = 0.f;
        #pragma unroll
        for (int i = 0; i < LL; i++) a += xq[j0 + i];
        float run = a;
        #pragma unroll
        for (int j = 0; j < 4; j++) {
            if (j > 0) run += xq[j0 + LL + j - 1] - xq[j0 + j - 1];
            ws[j0 + j] = (tbase + j0 + j < TP) ? run : CUDART_INF_F;
        }
    }
    __syncthreads();

    // ---- Main: warp wid computes rows [wid*32, wid*32+32), all 64 k ----
    const float* xw = xs + wid * 32 + g + t;   // a0 base
    const float* bw = sS + g * SSTR + t;       // b0 base

    float acc[2][8][4];
    #pragma unroll
    for (int m = 0; m < 2; m++)
        #pragma unroll
        for (int nt = 0; nt < 8; nt++)
            #pragma unroll
            for (int j = 0; j < 4; j++)
                acc[m][nt][j] = 0.f;

    #pragma unroll
    for (int l0 = 0; l0 < LL; l0 += 8) {
        u32 b0[8], b1[8];
        #pragma unroll
        for (int nt = 0; nt < 8; nt++) {
            b0[nt] = __float_as_uint(bw[nt * 8 * SSTR + l0]);
            b1[nt] = __float_as_uint(bw[nt * 8 * SSTR + l0 + 4]);
        }
        #pragma unroll
        for (int m = 0; m < 2; m++) {
            u32 a0 = __float_as_uint(xw[m * 16 + l0]);       // (g,   t)
            u32 a1 = __float_as_uint(xw[m * 16 + l0 + 8]);   // (g+8, t)
            u32 a2 = __float_as_uint(xw[m * 16 + l0 + 4]);   // (g,   t+4)
            u32 a3 = __float_as_uint(xw[m * 16 + l0 + 12]);  // (g+8, t+4)
            #pragma unroll
            for (int nt = 0; nt < 8; nt++)
                mma_tf32(acc[m][nt], a0, a1, a2, a3, b0[nt], b1[nt]);
        }
    }

    // ---- Epilogue: dist = ws - 2*corr, min over this warp's 32 rows ----
    float m16[16];
    #pragma unroll
    for (int i = 0; i < 16; i++) m16[i] = CUDART_INF_F;

    #pragma unroll
    for (int m = 0; m < 2; m++) {
        float w0 = ws[wid * 32 + m * 16 + g];
        float w1 = ws[wid * 32 + m * 16 + g + 8];
        #pragma unroll
        for (int nt = 0; nt < 8; nt++) {
            #pragma unroll
            for (int j = 0; j < 2; j++) {
                float v0 = fmaf(-2.f, acc[m][nt][j],     w0);
                float v1 = fmaf(-2.f, acc[m][nt][2 + j], w1);
                m16[nt * 2 + j] = fminf(m16[nt * 2 + j], fminf(v0, v1));
            }
        }
    }
    // reduce across g (lane bits 2..4); lanes with g==0 hold the result
    #pragma unroll
    for (int i = 0; i < 16; i++) {
        m16[i] = fminf(m16[i], __shfl_xor_sync(0xffffffffu, m16[i], 4));
        m16[i] = fminf(m16[i], __shfl_xor_sync(0xffffffffu, m16[i], 8));
        m16[i] = fminf(m16[i], __shfl_xor_sync(0xffffffffu, m16[i], 16));
    }
    if (g == 0) {
        #pragma unroll
        for (int nt = 0; nt < 8; nt++) {
            red[wid * KK + nt * 8 + 2 * t + 0] = m16[nt * 2 + 0];
            red[wid * KK + nt * 8 + 2 * t + 1] = m16[nt * 2 + 1];
        }
    }
    __syncthreads();

    if (tid < KK) {
        float m = red[tid];
        #pragma unroll
        for (int w = 1; w < 8; w++) m = fminf(m, red[w * KK + tid]);
        m += offs[tid];
        atomicMin((int*)&out[b * KK + tid], __float_as_int(m));
    }
}

extern "C" void kernel_launch(void* const* d_in, const int* in_sizes, int n_in,
                              void* d_out, int out_size) {
    const float* X = (const float*)d_in[0];   // (16, 8, 4096) f32
    const float* S = (const float*)d_in[1];   // (64, 128) f32
    float* out = (float*)d_out;               // (16, 64) f32

    init_out_kernel<<<(BB * KK + 255) / 256, 256>>>((int*)out);
    dim3 grid(NCHUNK, BB);
    shapelet_hmma_kernel<<<grid, 256>>>(X, S, out);
}

// round 5
// speedup vs baseline: 2.2754x; 1.0600x over previous
#include <cuda_runtime.h>
#include <cstdint>
#include <math_constants.h>

// Problem constants
#define BB 16
#define CC 8
#define TT 4096
#define KK 64
#define LL 128
#define TP (TT - LL + 1)        // 3969 valid sliding positions
#define TCHUNK 256              // t' per CTA
#define NCHUNK 16               // ceil(3969/256)
#define NSTEP 16                // 128 / 8 k per mma

typedef unsigned int u32;

__device__ __forceinline__ u32 f2tf32(float v) {
    u32 r;
    asm("cvt.rna.tf32.f32 %0, %1;" : "=r"(r) : "f"(v));
    return r;
}

__device__ __forceinline__ void mma_tf32(float* c, u32 a0, u32 a1, u32 a2, u32 a3,
                                         u32 b0, u32 b1) {
    asm volatile(
        "mma.sync.aligned.m16n8k8.row.col.f32.tf32.tf32.f32 "
        "{%0,%1,%2,%3}, {%4,%5,%6,%7}, {%8,%9}, {%0,%1,%2,%3};"
        : "+f"(c[0]), "+f"(c[1]), "+f"(c[2]), "+f"(c[3])
        : "r"(a0), "r"(a1), "r"(a2), "r"(a3), "r"(b0), "r"(b1));
}

__global__ void init_out_kernel(int* out) {
    int i = blockIdx.x * 256 + threadIdx.x;
    if (i < BB * KK) out[i] = 0x7F800000;  // +inf bits
}

__global__ __launch_bounds__(256, 2)
void shapelet_hmma_kernel(const float* __restrict__ X,
                          const float* __restrict__ S,
                          float* __restrict__ out) {
    // Pre-packed B fragments: sB2[kstep][nt][lane] = (b0, b1)
    __shared__ float2 sB2[NSTEP * 8 * 32];    // 32 KB
    __shared__ float xs[TCHUNK + LL];         // channel-sum of x (tf32-rounded)
    __shared__ float xq[TCHUNK + LL];         // channel-sum of x^2 (full f32)
    __shared__ float ws[TCHUNK];              // window sums (+inf past TP)
    __shared__ float offs[KK];                // C * sum_l s^2
    __shared__ float red[8 * KK];             // per-warp partial mins

    const int tid  = threadIdx.x;
    const int wid  = tid >> 5;
    const int lane = tid & 31;
    const int g    = lane >> 2;          // groupID 0..7
    const int t    = lane & 3;           // threadID_in_group 0..3
    const int b    = blockIdx.y;
    const int tbase = blockIdx.x * TCHUNK;

    // ---- Prologue 1: B fragments packed from global S + shapelet norms ----
    {
        int nt  = wid;                   // 0..7 (n-tile)
        int row = nt * 8 + g;            // shapelet index k
        const float* Sr = S + row * LL + t;
        float ns = 0.f;
        #pragma unroll
        for (int j = 0; j < NSTEP; j++) {
            float s0 = Sr[j * 8];
            float s1 = Sr[j * 8 + 4];
            ns += s0 * s0 + s1 * s1;
            float2 v;
            v.x = __uint_as_float(f2tf32(s0));
            v.y = __uint_as_float(f2tf32(s1));
            sB2[j * 256 + nt * 32 + lane] = v;
        }
        ns += __shfl_xor_sync(0xffffffffu, ns, 1);
        ns += __shfl_xor_sync(0xffffffffu, ns, 2);
        if (t == 0) offs[row] = (float)CC * ns;
    }

    // ---- Prologue 2: channel sums for t in [tbase, tbase+384) ----
    for (int j = tid; j < TCHUNK + LL; j += 256) {
        int tg = tbase + j;
        float sm = 0.f, sq = 0.f;
        if (tg < TT) {
            #pragma unroll
            for (int c = 0; c < CC; c++) {
                float v = X[((b * CC + c) << 12) + tg];
                sm += v; sq += v * v;
            }
        }
        xs[j] = __uint_as_float(f2tf32(sm));
        xq[j] = sq;
    }
    __syncthreads();

    // ---- Prologue 3: sliding window sums, fully parallel (ILP-4) ----
    {
        float s0 = 0.f, s1 = 0.f, s2 = 0.f, s3 = 0.f;
        #pragma unroll
        for (int i = 0; i < LL; i += 4) {
            s0 += xq[tid + i];
            s1 += xq[tid + i + 1];
            s2 += xq[tid + i + 2];
            s3 += xq[tid + i + 3];
        }
        float w = (s0 + s1) + (s2 + s3);
        ws[tid] = (tbase + tid < TP) ? w : CUDART_INF_F;
    }
    __syncthreads();

    // ---- Main: warp wid computes rows [wid*32, wid*32+32), all 64 k ----
    const float* xw = xs + wid * 32 + g + t;

    float acc[2][8][4];
    #pragma unroll
    for (int m = 0; m < 2; m++)
        #pragma unroll
        for (int nt = 0; nt < 8; nt++)
            #pragma unroll
            for (int j = 0; j < 4; j++)
                acc[m][nt][j] = 0.f;

    // rolling A fragments: a1(l0) == a0(l0+8), a3(l0) == a2(l0+8)
    float a0r[2], a2r[2];
    #pragma unroll
    for (int m = 0; m < 2; m++) { a0r[m] = xw[m * 16]; a2r[m] = xw[m * 16 + 4]; }

    #pragma unroll
    for (int s = 0; s < NSTEP; s++) {
        const int l0 = s * 8;
        float2 bv[8];
        const float2* bp = sB2 + s * 256 + lane;
        #pragma unroll
        for (int nt = 0; nt < 8; nt++) bv[nt] = bp[nt * 32];
        #pragma unroll
        for (int m = 0; m < 2; m++) {
            float a1 = xw[m * 16 + l0 + 8];
            float a3 = xw[m * 16 + l0 + 12];
            #pragma unroll
            for (int nt = 0; nt < 8; nt++)
                mma_tf32(acc[m][nt],
                         __float_as_uint(a0r[m]), __float_as_uint(a1),
                         __float_as_uint(a2r[m]), __float_as_uint(a3),
                         __float_as_uint(bv[nt].x), __float_as_uint(bv[nt].y));
            a0r[m] = a1; a2r[m] = a3;
        }
    }

    // ---- Epilogue: dist = ws - 2*corr, min over this warp's 32 rows ----
    float m16[16];
    #pragma unroll
    for (int i = 0; i < 16; i++) m16[i] = CUDART_INF_F;

    #pragma unroll
    for (int m = 0; m < 2; m++) {
        float w0 = ws[wid * 32 + m * 16 + g];
        float w1 = ws[wid * 32 + m * 16 + g + 8];
        #pragma unroll
        for (int nt = 0; nt < 8; nt++) {
            #pragma unroll
            for (int j = 0; j < 2; j++) {
                float v0 = fmaf(-2.f, acc[m][nt][j],     w0);
                float v1 = fmaf(-2.f, acc[m][nt][2 + j], w1);
                m16[nt * 2 + j] = fminf(m16[nt * 2 + j], fminf(v0, v1));
            }
        }
    }
    // reduce across g (lane bits 2..4)
    #pragma unroll
    for (int i = 0; i < 16; i++) {
        m16[i] = fminf(m16[i], __shfl_xor_sync(0xffffffffu, m16[i], 4));
        m16[i] = fminf(m16[i], __shfl_xor_sync(0xffffffffu, m16[i], 8));
        m16[i] = fminf(m16[i], __shfl_xor_sync(0xffffffffu, m16[i], 16));
    }
    if (g == 0) {
        #pragma unroll
        for (int nt = 0; nt < 8; nt++) {
            red[wid * KK + nt * 8 + 2 * t + 0] = m16[nt * 2 + 0];
            red[wid * KK + nt * 8 + 2 * t + 1] = m16[nt * 2 + 1];
        }
    }
    __syncthreads();

    if (tid < KK) {
        float m = red[tid];
        #pragma unroll
        for (int w = 1; w < 8; w++) m = fminf(m, red[w * KK + tid]);
        m += offs[tid];
        atomicMin((int*)&out[b * KK + tid], __float_as_int(m));
    }
}

extern "C" void kernel_launch(void* const* d_in, const int* in_sizes, int n_in,
                              void* d_out, int out_size) {
    const float* X = (const float*)d_in[0];   // (16, 8, 4096) f32
    const float* S = (const float*)d_in[1];   // (64, 128) f32
    float* out = (float*)d_out;               // (16, 64) f32

    init_out_kernel<<<(BB * KK + 255) / 256, 256>>>((int*)out);
    dim3 grid(NCHUNK, BB);
    shapelet_hmma_kernel<<<grid, 256>>>(X, S, out);
}

// round 6
// speedup vs baseline: 2.8398x; 1.2481x over previous
#include <cuda_runtime.h>
#include <cuda_bf16.h>
#include <cstdint>
#include <math_constants.h>

// Problem constants
#define BB 16
#define CC 8
#define TT 4096
#define KK 64
#define LL 128
#define TP (TT - LL + 1)        // 3969 valid sliding positions
#define TCHUNK 256              // t' per CTA
#define NCHUNK 16               // ceil(3969/256)
#define NSTEP 8                 // 128 / 16 k per bf16 mma

typedef unsigned int u32;

__device__ __forceinline__ u32 pack_bf16(float a, float b) {
    __nv_bfloat162 h = __floats2bfloat162_rn(a, b);
    return *(u32*)&h;
}

__device__ __forceinline__ void mma_bf16(float* c, u32 a0, u32 a1, u32 a2, u32 a3,
                                         u32 b0, u32 b1) {
    asm volatile(
        "mma.sync.aligned.m16n8k16.row.col.f32.bf16.bf16.f32 "
        "{%0,%1,%2,%3}, {%4,%5,%6,%7}, {%8,%9}, {%0,%1,%2,%3};"
        : "+f"(c[0]), "+f"(c[1]), "+f"(c[2]), "+f"(c[3])
        : "r"(a0), "r"(a1), "r"(a2), "r"(a3), "r"(b0), "r"(b1));
}

__global__ void init_out_kernel(int* out) {
    int i = blockIdx.x * 256 + threadIdx.x;
    if (i < BB * KK) out[i] = 0x7F800000;  // +inf bits
}

__global__ __launch_bounds__(256, 2)
void shapelet_bf16_kernel(const float* __restrict__ X,
                          const float* __restrict__ S,
                          float* __restrict__ out) {
    __shared__ uint2 sB[NSTEP * 8 * 32];   // [step][nt][lane] = (b0,b1)  16 KB
    __shared__ float xs[TCHUNK + LL + 1];  // channel-sum (f32); [384]=0 pad
    __shared__ float xq[TCHUNK + LL];      // channel-sum of x^2
    __shared__ u32   ea[200];              // half2(xs[2j], xs[2j+1])
    __shared__ u32   oa[200];              // half2(xs[2j+1], xs[2j+2])
    __shared__ float pscan[TCHUNK + LL];   // per-32-seg inclusive scans of xq
    __shared__ float segt[12];             // segment totals
    __shared__ float ws[TCHUNK];           // window sums (+inf past TP)
    __shared__ float offs[KK];             // C * sum_l s^2
    __shared__ float red[8 * KK];          // per-warp partial mins

    const int tid  = threadIdx.x;
    const int wid  = tid >> 5;
    const int lane = tid & 31;
    const int g    = lane >> 2;            // groupID 0..7
    const int t    = lane & 3;             // threadID_in_group 0..3
    const int b    = blockIdx.y;
    const int tbase = blockIdx.x * TCHUNK;

    // ---- Prologue 1: B fragments (bf16) from global S + shapelet norms ----
    {
        int nt  = wid;                     // n-tile 0..7
        int row = nt * 8 + g;              // shapelet index
        const float2* Sr = (const float2*)(S + row * LL);
        float ns = 0.f;
        #pragma unroll
        for (int s = 0; s < NSTEP; s++) {
            float2 p = Sr[s * 8 + t];          // S[row][16s+2t], +1
            float2 q = Sr[s * 8 + 4 + t];      // S[row][16s+8+2t], +1
            ns += p.x * p.x + p.y * p.y + q.x * q.x + q.y * q.y;
            uint2 v;
            v.x = pack_bf16(p.x, p.y);
            v.y = pack_bf16(q.x, q.y);
            sB[s * 256 + nt * 32 + lane] = v;
        }
        ns += __shfl_xor_sync(0xffffffffu, ns, 1);
        ns += __shfl_xor_sync(0xffffffffu, ns, 2);
        if (t == 0) offs[row] = (float)CC * ns;
    }

    // ---- Prologue 2: channel sums for t in [tbase, tbase+384) ----
    for (int j = tid; j < TCHUNK + LL; j += 256) {
        int tg = tbase + j;
        float sm = 0.f, sq = 0.f;
        if (tg < TT) {
            #pragma unroll
            for (int c = 0; c < CC; c++) {
                float v = X[((b * CC + c) << 12) + tg];
                sm += v; sq += v * v;
            }
        }
        xs[j] = sm; xq[j] = sq;
    }
    if (tid == 0) xs[TCHUNK + LL] = 0.f;
    __syncthreads();

    // ---- Prologue 3a: parity-aligned bf16 pair arrays for A fragments ----
    if (tid < 192) {
        float x0 = xs[2 * tid], x1 = xs[2 * tid + 1], x2 = xs[2 * tid + 2];
        ea[tid] = pack_bf16(x0, x1);
        oa[tid] = pack_bf16(x1, x2);
    }

    // ---- Prologue 3b: segmented scan of xq (12 segments of 32) ----
    for (int seg = wid; seg < 12; seg += 8) {
        float v = xq[seg * 32 + lane];
        #pragma unroll
        for (int o = 1; o < 32; o <<= 1) {
            float u = __shfl_up_sync(0xffffffffu, v, o);
            if (lane >= o) v += u;
        }
        pscan[seg * 32 + lane] = v;
        if (lane == 31) segt[seg] = v;
    }
    __syncthreads();

    // ---- ws[t'] = sum_{i=t'}^{t'+127} xq[i], via segment decomposition ----
    {
        int q = tid >> 5, r = tid & 31;
        float suf  = segt[q] - (pscan[tid] - xq[tid]);
        float mid  = segt[q + 1] + segt[q + 2] + segt[q + 3];
        float head = (r == 0) ? 0.f : pscan[(q + 4) * 32 + r - 1];
        float w = suf + mid + head;
        ws[tid] = (tbase + tid < TP) ? w : CUDART_INF_F;
    }
    __syncthreads();

    // ---- Main: warp wid computes rows [wid*32, wid*32+32), all 64 k ----
    // A fragments: a0=v(i0), a1=a2=v(i0+8), a3=v(i0+16), i0 parity fixed = g&1
    const u32* ap = (g & 1) ? oa : ea;
    int j0[2]; u32 r0[2], r1[2];
    #pragma unroll
    for (int m = 0; m < 2; m++) {
        int i0 = wid * 32 + m * 16 + g + 2 * t;
        j0[m] = i0 >> 1;
        r0[m] = ap[j0[m]];
        r1[m] = ap[j0[m] + 4];
    }

    float acc[2][8][4];
    #pragma unroll
    for (int m = 0; m < 2; m++)
        #pragma unroll
        for (int nt = 0; nt < 8; nt++)
            #pragma unroll
            for (int j = 0; j < 4; j++)
                acc[m][nt][j] = 0.f;

    #pragma unroll
    for (int s = 0; s < NSTEP; s++) {
        uint2 bv[8];
        const uint2* bp = sB + s * 256 + lane;
        #pragma unroll
        for (int nt = 0; nt < 8; nt++) bv[nt] = bp[nt * 32];
        #pragma unroll
        for (int m = 0; m < 2; m++) {
            u32 r2 = ap[j0[m] + 8 * s + 8];
            #pragma unroll
            for (int nt = 0; nt < 8; nt++)
                mma_bf16(acc[m][nt], r0[m], r1[m], r1[m], r2, bv[nt].x, bv[nt].y);
            r0[m] = r2;
            if (s < NSTEP - 1) r1[m] = ap[j0[m] + 8 * s + 12];
        }
    }

    // ---- Epilogue: dist = ws - 2*corr, min over this warp's 32 rows ----
    float m16[16];
    #pragma unroll
    for (int i = 0; i < 16; i++) m16[i] = CUDART_INF_F;

    #pragma unroll
    for (int m = 0; m < 2; m++) {
        float w0 = ws[wid * 32 + m * 16 + g];
        float w1 = ws[wid * 32 + m * 16 + g + 8];
        #pragma unroll
        for (int nt = 0; nt < 8; nt++) {
            #pragma unroll
            for (int j = 0; j < 2; j++) {
                float v0 = fmaf(-2.f, acc[m][nt][j],     w0);
                float v1 = fmaf(-2.f, acc[m][nt][2 + j], w1);
                m16[nt * 2 + j] = fminf(m16[nt * 2 + j], fminf(v0, v1));
            }
        }
    }
    // reduce across g (lane bits 2..4)
    #pragma unroll
    for (int i = 0; i < 16; i++) {
        m16[i] = fminf(m16[i], __shfl_xor_sync(0xffffffffu, m16[i], 4));
        m16[i] = fminf(m16[i], __shfl_xor_sync(0xffffffffu, m16[i], 8));
        m16[i] = fminf(m16[i], __shfl_xor_sync(0xffffffffu, m16[i], 16));
    }
    if (g == 0) {
        #pragma unroll
        for (int nt = 0; nt < 8; nt++) {
            red[wid * KK + nt * 8 + 2 * t + 0] = m16[nt * 2 + 0];
            red[wid * KK + nt * 8 + 2 * t + 1] = m16[nt * 2 + 1];
        }
    }
    __syncthreads();

    if (tid < KK) {
        float m = red[tid];
        #pragma unroll
        for (int w = 1; w < 8; w++) m = fminf(m, red[w * KK + tid]);
        m += offs[tid];
        atomicMin((int*)&out[b * KK + tid], __float_as_int(m));
    }
}

extern "C" void kernel_launch(void* const* d_in, const int* in_sizes, int n_in,
                              void* d_out, int out_size) {
    const float* X = (const float*)d_in[0];   // (16, 8, 4096) f32
    const float* S = (const float*)d_in[1];   // (64, 128) f32
    float* out = (float*)d_out;               // (16, 64) f32

    init_out_kernel<<<(BB * KK + 255) / 256, 256>>>((int*)out);
    dim3 grid(NCHUNK, BB);
    shapelet_bf16_kernel<<<grid, 256>>>(X, S, out);
}